// round 6
// baseline (speedup 1.0000x reference)
#include <cuda_runtime.h>

// predictor_interp2d: nearest-neighbor gather from N=1024 points onto a 256x256 grid.
// d_in[0] = R_pc  [B=2, C=4, N=1024] float32
// d_in[1] = XY_pc [B=2, 2, N=1024]   float32
// d_out   = R_grd [B=2, C=4, 256, 256] float32
//
// Single fused kernel: one 512-thread block per PAIR of adjacent 16x16-cell bin
// tiles (256 blocks). Each block redundantly bins all 1024 points of its batch
// into a block-local 16x16 CSR in shared memory, then runs a warp-uniform
// expanding-ring NN search (warps 0-7 -> tile 2k, warps 8-15 -> tile 2k+1) with
// per-warp termination (no barriers in the search phase). Candidate d2 uses the
// EXACT reference arithmetic (bit-matched since R2); exact ties resolve to the
// smallest point index == jnp.argmin first-min semantics, so atomic scatter
// order cannot affect the output.

#define NPTS  1024
#define NB    16
#define BINW  0.0625f

__global__ __launch_bounds__(512, 2)
void nn_fused(const float* __restrict__ XY,
              const float* __restrict__ R,
              float* __restrict__ out) {
    __shared__ float4 spts[NPTS];       // {px, py, s, index-as-bits}, bin-ordered
    __shared__ int    soff[NB*NB + 1];  // CSR offsets
    __shared__ int    scnt[NB*NB];      // counts, then scatter cursors
    __shared__ int    swsum[8];         // per-warp scan partials

    const int t    = threadIdx.x;
    const int b    = blockIdx.x >> 7;           // 128 tile-pairs per batch
    const int pair = blockIdx.x & 127;

    // ---- Phase 1: block-local binning of all 1024 points (2 per thread) ----
    const float* xy = XY + b * (2 * NPTS);
    float px[2], py[2]; int pbin[2];

    if (t < 256) scnt[t] = 0;
    __syncthreads();
    #pragma unroll
    for (int j = 0; j < 2; ++j) {
        const int i = t + j * 512;
        const float x = xy[i];
        const float y = xy[NPTS + i];
        const int bxx = min(max((int)(x * 16.0f), 0), NB - 1);
        const int byy = min(max((int)(y * 16.0f), 0), NB - 1);
        px[j] = x; py[j] = y; pbin[j] = byy * NB + bxx;
        atomicAdd(&scnt[pbin[j]], 1);
    }
    __syncthreads();

    // Two-level exclusive scan over 256 counts (warps 0-7; warp-uniform branch).
    if (t < 256) {
        const int v = scnt[t];
        int incl = v;
        #pragma unroll
        for (int d = 1; d < 32; d <<= 1) {
            const int n = __shfl_up_sync(0xffffffffu, incl, d);
            if ((t & 31) >= d) incl += n;
        }
        if ((t & 31) == 31) swsum[t >> 5] = incl;
        __syncthreads();
        if (t < 32) {
            const int w = (t < 8) ? swsum[t] : 0;
            int iw = w;
            #pragma unroll
            for (int d = 1; d < 8; d <<= 1) {
                const int n = __shfl_up_sync(0xffffffffu, iw, d);
                if (t >= d) iw += n;
            }
            if (t < 8) swsum[t] = iw - w;       // exclusive warp base
        }
        __syncthreads();
        soff[t] = incl - v + swsum[t >> 5];     // exclusive prefix for bin t
        if (t == 0) soff[NB*NB] = NPTS;
        scnt[t] = 0;                            // reuse as scatter cursor
    } else {
        __syncthreads();
        __syncthreads();
    }
    __syncthreads();

    #pragma unroll
    for (int j = 0; j < 2; ++j) {
        const int i   = t + j * 512;
        const int pos = soff[pbin[j]] + atomicAdd(&scnt[pbin[j]], 1);
        // s with the reference's rounding order (mul, mul, add)
        const float s = __fadd_rn(__fmul_rn(px[j], px[j]), __fmul_rn(py[j], py[j]));
        spts[pos] = make_float4(px[j], py[j], s, __int_as_float(i));
    }
    __syncthreads();

    // ---- Phase 2: expanding-ring NN search (warp-uniform, barrier-free) ----
    const int sel = t >> 8;                     // 0: warps 0-7, 1: warps 8-15
    const int bin = pair * 2 + sel;             // warp-uniform home bin
    const int bx  = bin & (NB - 1);
    const int by  = bin >> 4;
    const int u   = t & 255;
    const int lx  = u & 15, ly = u >> 4;
    const int cx  = bx * 16 + lx;
    const int cy  = by * 16 + ly;
    const int cell = cy * 256 + cx;

    const float inv = 1.0f / 256.0f;
    const float gx = ((float)cx + 0.5f) * inv;
    const float gy = ((float)cy + 0.5f) * inv;
    const float g2 = gx * gx + gy * gy;         // geometry bound only

    float best = 3.402823466e38f;
    int   bi   = 0;

    #define SCAN_RANGE(E0, E1)                                                  \
        _Pragma("unroll 2")                                                     \
        for (int k = (E0); k < (E1); ++k) {                                     \
            const float4 p = spts[k];                                           \
            const float dot = __fmaf_rn(p.y, gy, __fmul_rn(p.x, gx));           \
            const float d   = __fmaf_rn(-2.0f, dot, p.z);                       \
            const int   i   = __float_as_int(p.w);                              \
            if (d < best) { best = d; bi = i; }                                 \
            else if (d == best && i < bi) { bi = i; }                           \
        }

    for (int r = 0; r < NB; ++r) {
        if (r > 0) {
            // Per-thread bound: distance to the boundary of the scanned bin square
            // [bx-(r-1), bx+(r-1)]^2; domain-edge faces excluded. Unscanned points
            // have computed d2 >= f^2 - g2 - eps; slack 1e-4 >> eps forbids any
            // unscanned point from beating OR tying the current winner, so extra
            // rings scanned for warp-mates can never change this thread's result.
            const float fL = (bx - (r - 1) >= 1)      ? (gx - (float)(bx - (r - 1)) * BINW) : 1e30f;
            const float fR = (bx + (r - 1) <= NB - 2) ? ((float)(bx + r) * BINW - gx)       : 1e30f;
            const float fB = (by - (r - 1) >= 1)      ? (gy - (float)(by - (r - 1)) * BINW) : 1e30f;
            const float fT = (by + (r - 1) <= NB - 2) ? ((float)(by + r) * BINW - gy)       : 1e30f;
            const float f  = fminf(fminf(fL, fR), fminf(fB, fT));
            const int cont = !(f * f > best + g2 + 1e-4f);
            if (!__any_sync(0xffffffffu, cont)) break;   // per-warp exit
        }
        const int x0 = max(bx - r, 0), x1 = min(bx + r, NB - 1);
        const int y0 = max(by - r, 0), y1 = min(by + r, NB - 1);
        for (int yb = y0; yb <= y1; ++yb) {
            if (yb == by - r || yb == by + r) {
                // Full ring row: bins x0..x1 are CSR-contiguous -> one flat segment.
                const int e0 = soff[yb * NB + x0];
                const int e1 = soff[yb * NB + x1 + 1];
                SCAN_RANGE(e0, e1)
            } else {
                // Middle row: only the two ring columns.
                if (bx - r >= 0) {
                    const int bb = yb * NB + (bx - r);
                    SCAN_RANGE(soff[bb], soff[bb + 1])
                }
                if (bx + r <= NB - 1) {
                    const int bb = yb * NB + (bx + r);
                    SCAN_RANGE(soff[bb], soff[bb + 1])
                }
            }
        }
    }
    #undef SCAN_RANGE

    // ---- Phase 3: gather 4 channels (R is 16 KB, L2-resident) ----
    const float* Rb = R   + b * (4 * NPTS);
    float*       ob = out + b * (4 * 65536);
    #pragma unroll
    for (int c = 0; c < 4; ++c)
        ob[c * 65536 + cell] = __ldg(&Rb[c * NPTS + bi]);
}

extern "C" void kernel_launch(void* const* d_in, const int* in_sizes, int n_in,
                              void* d_out, int out_size) {
    const float* R  = (const float*)d_in[0];   // [2,4,1024]
    const float* XY = (const float*)d_in[1];   // [2,2,1024]
    float* out = (float*)d_out;                // [2,4,256,256]

    nn_fused<<<256, 512>>>(XY, R, out);
}

// round 7
// speedup vs baseline: 1.0683x; 1.0683x over previous
#include <cuda_runtime.h>

// predictor_interp2d: nearest-neighbor gather from N=1024 points onto a 256x256 grid.
// d_in[0] = R_pc  [B=2, C=4, N=1024] float32
// d_in[1] = XY_pc [B=2, 2, N=1024]   float32
// d_out   = R_grd [B=2, C=4, 256, 256] float32
//
// Single fused kernel: one 1024-thread block per QUAD of adjacent 16x16-cell bin
// tiles (128 blocks, one per SM, single wave). Each block redundantly bins all
// 1024 points of its batch into a block-local 16x16 CSR in shared memory
// (1 point/thread), then runs a warp-uniform expanding-ring NN search
// (warp group w>>3 -> tile 4k + (t>>8)) with per-warp termination.
//
// Argmin is branch-free: key = (ordered_uint(d2) << 32) | point_index, reduced
// with u64 min. The ordered-uint transform is strictly monotone on non-NaN
// floats, so lexicographic min == (min d2, then min index) == jnp.argmin
// first-min semantics. d2 uses the EXACT reference arithmetic (bit-matched
// since R2), so the result is bit-identical and scatter order irrelevant.

#define NPTS  1024
#define NB    16
#define BINW  0.0625f

__global__ __launch_bounds__(1024, 1)
void nn_fused(const float* __restrict__ XY,
              const float* __restrict__ R,
              float* __restrict__ out) {
    __shared__ float4 spts[NPTS];       // {px, py, s, index-as-bits}, bin-ordered
    __shared__ int    soff[NB*NB + 1];  // CSR offsets
    __shared__ int    scnt[NB*NB];      // counts, then scatter cursors
    __shared__ int    swsum[8];         // per-warp scan partials

    const int t    = threadIdx.x;
    const int b    = blockIdx.x >> 6;           // 64 tile-quads per batch
    const int quad = blockIdx.x & 63;

    // ---- Phase 1: block-local binning of all 1024 points (1 per thread) ----
    const float* xy = XY + b * (2 * NPTS);

    if (t < 256) scnt[t] = 0;
    __syncthreads();

    const float x = xy[t];
    const float y = xy[NPTS + t];
    const int bxx = min(max((int)(x * 16.0f), 0), NB - 1);
    const int byy = min(max((int)(y * 16.0f), 0), NB - 1);
    const int pbin = byy * NB + bxx;
    atomicAdd(&scnt[pbin], 1);
    __syncthreads();

    // Two-level exclusive scan over 256 counts (warps 0-7; warp-uniform branch).
    if (t < 256) {
        const int v = scnt[t];
        int incl = v;
        #pragma unroll
        for (int d = 1; d < 32; d <<= 1) {
            const int n = __shfl_up_sync(0xffffffffu, incl, d);
            if ((t & 31) >= d) incl += n;
        }
        if ((t & 31) == 31) swsum[t >> 5] = incl;
        __syncthreads();
        if (t < 32) {
            const int w = (t < 8) ? swsum[t] : 0;
            int iw = w;
            #pragma unroll
            for (int d = 1; d < 8; d <<= 1) {
                const int n = __shfl_up_sync(0xffffffffu, iw, d);
                if (t >= d) iw += n;
            }
            if (t < 8) swsum[t] = iw - w;       // exclusive warp base
        }
        __syncthreads();
        soff[t] = incl - v + swsum[t >> 5];     // exclusive prefix for bin t
        if (t == 0) soff[NB*NB] = NPTS;
        scnt[t] = 0;                            // reuse as scatter cursor
    } else {
        __syncthreads();
        __syncthreads();
    }
    __syncthreads();

    {
        const int pos = soff[pbin] + atomicAdd(&scnt[pbin], 1);
        // s with the reference's rounding order (mul, mul, add)
        const float s = __fadd_rn(__fmul_rn(x, x), __fmul_rn(y, y));
        spts[pos] = make_float4(x, y, s, __int_as_float(t));
    }
    __syncthreads();

    // ---- Phase 2: expanding-ring NN search (warp-uniform, barrier-free) ----
    const int sel = t >> 8;                     // 0..3: 8-warp group per tile
    const int bin = quad * 4 + sel;             // warp-uniform home bin
    const int bx  = bin & (NB - 1);
    const int by  = bin >> 4;
    const int u   = t & 255;
    const int lx  = u & 15, ly = u >> 4;
    const int cx  = bx * 16 + lx;
    const int cy  = by * 16 + ly;
    const int cell = cy * 256 + cx;

    const float inv = 1.0f / 256.0f;
    const float gx = ((float)cx + 0.5f) * inv;
    const float gy = ((float)cy + 0.5f) * inv;
    const float g2 = gx * gx + gy * gy;         // geometry bound only

    // Packed (ordered d2, index) key; u64 min == lexicographic first-min.
    unsigned long long bestk = 0xFFFFFFFFFFFFFFFFull;

    #define SCAN_RANGE(E0, E1)                                                  \
        _Pragma("unroll 2")                                                     \
        for (int k = (E0); k < (E1); ++k) {                                     \
            const float4 p = spts[k];                                           \
            const float dot = __fmaf_rn(p.y, gy, __fmul_rn(p.x, gx));           \
            const float d   = __fmaf_rn(-2.0f, dot, p.z);                       \
            unsigned int ub = __float_as_uint(d);                               \
            ub ^= (unsigned int)(((int)ub >> 31)) | 0x80000000u;                \
            const unsigned long long key =                                      \
                ((unsigned long long)ub << 32) | __float_as_uint(p.w);          \
            bestk = min(bestk, key);                                            \
        }

    for (int r = 0; r < NB; ++r) {
        if (r > 0) {
            // Decode current best d2 (NaN if nothing scanned yet -> keep going).
            const unsigned int ob = (unsigned int)(bestk >> 32);
            const unsigned int fb = (ob & 0x80000000u) ? (ob ^ 0x80000000u) : ~ob;
            const float best = __uint_as_float(fb);
            // Per-thread bound: distance to the boundary of the scanned bin square
            // [bx-(r-1), bx+(r-1)]^2; domain-edge faces excluded. Unscanned points
            // have computed d2 >= f^2 - g2 - eps; slack 1e-4 >> eps forbids any
            // unscanned point from beating OR tying the current winner, so extra
            // rings scanned for warp-mates can never change this thread's result.
            const float fL = (bx - (r - 1) >= 1)      ? (gx - (float)(bx - (r - 1)) * BINW) : 1e30f;
            const float fR = (bx + (r - 1) <= NB - 2) ? ((float)(bx + r) * BINW - gx)       : 1e30f;
            const float fB = (by - (r - 1) >= 1)      ? (gy - (float)(by - (r - 1)) * BINW) : 1e30f;
            const float fT = (by + (r - 1) <= NB - 2) ? ((float)(by + r) * BINW - gy)       : 1e30f;
            const float f  = fminf(fminf(fL, fR), fminf(fB, fT));
            const int cont = !(f * f > best + g2 + 1e-4f);   // NaN best -> cont
            if (!__any_sync(0xffffffffu, cont)) break;       // per-warp exit
        }
        const int x0 = max(bx - r, 0), x1 = min(bx + r, NB - 1);
        const int y0 = max(by - r, 0), y1 = min(by + r, NB - 1);
        for (int yb = y0; yb <= y1; ++yb) {
            if (yb == by - r || yb == by + r) {
                // Full ring row: bins x0..x1 are CSR-contiguous -> one flat segment.
                const int e0 = soff[yb * NB + x0];
                const int e1 = soff[yb * NB + x1 + 1];
                SCAN_RANGE(e0, e1)
            } else {
                // Middle row: only the two ring columns.
                if (bx - r >= 0) {
                    const int bb = yb * NB + (bx - r);
                    SCAN_RANGE(soff[bb], soff[bb + 1])
                }
                if (bx + r <= NB - 1) {
                    const int bb = yb * NB + (bx + r);
                    SCAN_RANGE(soff[bb], soff[bb + 1])
                }
            }
        }
    }
    #undef SCAN_RANGE

    const int bi = (int)(bestk & 0xFFFFFFFFull);

    // ---- Phase 3: gather 4 channels (R is 16 KB, L2-resident) ----
    const float* Rb = R   + b * (4 * NPTS);
    float*       ob = out + b * (4 * 65536);
    #pragma unroll
    for (int c = 0; c < 4; ++c)
        ob[c * 65536 + cell] = __ldg(&Rb[c * NPTS + bi]);
}

extern "C" void kernel_launch(void* const* d_in, const int* in_sizes, int n_in,
                              void* d_out, int out_size) {
    const float* R  = (const float*)d_in[0];   // [2,4,1024]
    const float* XY = (const float*)d_in[1];   // [2,2,1024]
    float* out = (float*)d_out;                // [2,4,256,256]

    nn_fused<<<128, 1024>>>(XY, R, out);
}